// round 3
// baseline (speedup 1.0000x reference)
#include <cuda_runtime.h>
#include <math.h>

#define D_MODEL 512
#define T_LEN   2048
#define BATCH   4
#define NROWS   (BATCH * T_LEN)   // 8192
#define N_HEADS 8
#define D_K     64

// -------- scratch (no allocs allowed in kernel_launch) --------
__device__ float g_h[NROWS * D_MODEL];  // LN1(x)+PE  (residual1)
__device__ float g_q[NROWS * D_MODEL];  // [B,H,T,64]
__device__ float g_k[NROWS * D_MODEL];
__device__ float g_v[NROWS * D_MODEL];
__device__ float g_o[NROWS * D_MODEL];  // attention output, [B,T,512]
__device__ float g_y[NROWS * D_MODEL];  // o @ wfc

// ============================================================
// Kernel 1: LayerNorm(eps=1e-5) + sinusoidal positional encoding
// one block per row (512 elems), 128 threads, float4 per thread
// ============================================================
__global__ __launch_bounds__(128) void ln1_pe_kernel(
    const float* __restrict__ x,
    const float* __restrict__ gam,
    const float* __restrict__ bet,
    float* __restrict__ h_out)
{
    int r   = blockIdx.x;
    int tid = threadIdx.x;
    const float4 xv = ((const float4*)(x + (size_t)r * D_MODEL))[tid];

    float sum = xv.x + xv.y + xv.z + xv.w;
    float sq  = xv.x*xv.x + xv.y*xv.y + xv.z*xv.z + xv.w*xv.w;
    #pragma unroll
    for (int off = 16; off; off >>= 1) {
        sum += __shfl_xor_sync(0xffffffffu, sum, off);
        sq  += __shfl_xor_sync(0xffffffffu, sq,  off);
    }
    __shared__ float s1[4], s2[4];
    if ((tid & 31) == 0) { s1[tid >> 5] = sum; s2[tid >> 5] = sq; }
    __syncthreads();
    sum = s1[0] + s1[1] + s1[2] + s1[3];
    sq  = s2[0] + s2[1] + s2[2] + s2[3];

    float mean = sum * (1.0f / D_MODEL);
    float var  = sq  * (1.0f / D_MODEL) - mean * mean;
    float rstd = rsqrtf(var + 1e-5f);

    int t  = r & (T_LEN - 1);
    int c0 = tid * 4;
    const float* xp = (const float*)&xv;
    float4 hv;
    float* hp = (float*)&hv;
    #pragma unroll
    for (int u = 0; u < 4; u++) {
        int c = c0 + u;
        // div_term = exp(-(c&~1) * ln(10000)/512), computed in fp32 like numpy
        float div = expf((float)(c & ~1) * (-9.2103403719761836f / 512.0f));
        float ang = (float)t * div;
        float pe  = (c & 1) ? cosf(ang) : sinf(ang);
        hp[u] = (xp[u] - mean) * rstd * gam[c] + bet[c] + pe;
    }
    ((float4*)(h_out + (size_t)r * D_MODEL))[tid] = hv;
}

// ============================================================
// Kernel 2: tiled fp32 GEMM  C[8192,512] = A[8192,512] @ B[512,512]
// BM=BN=64, BK=32, 256 threads, 4x4 micro-tile per thread.
// MODE 0: plain row-major output.  MODE 1: scatter to [B,H,T,64].
// ============================================================
template<int MODE>
__global__ __launch_bounds__(256) void gemm_k(
    const float* __restrict__ A,
    const float* __restrict__ B,
    float* __restrict__ C)
{
    const int K = 512, N = 512;
    __shared__ float sA[32][65];   // [k][m], padded
    __shared__ float sB[32][64];   // [k][n]

    int tid = threadIdx.x;
    int tx  = tid & 15;
    int ty  = tid >> 4;
    int n0  = blockIdx.x * 64;
    int m0  = blockIdx.y * 64;

    int aRow  = tid >> 3;      // 0..31
    int aCol4 = tid & 7;       // 0..7  (float4 along K)
    int bRow  = tid >> 4;      // 0..15
    int bCol4 = tid & 15;      // 0..15 (float4 along N)

    float acc[4][4] = {};

    for (int k0 = 0; k0 < K; k0 += 32) {
        float4 a0 = *(const float4*)(A + (size_t)(m0 + aRow)      * K + k0 + aCol4 * 4);
        float4 a1 = *(const float4*)(A + (size_t)(m0 + aRow + 32) * K + k0 + aCol4 * 4);
        float4 b0 = *(const float4*)(B + (size_t)(k0 + bRow)      * N + n0 + bCol4 * 4);
        float4 b1 = *(const float4*)(B + (size_t)(k0 + bRow + 16) * N + n0 + bCol4 * 4);
        __syncthreads();
        sA[aCol4*4+0][aRow]      = a0.x;
        sA[aCol4*4+1][aRow]      = a0.y;
        sA[aCol4*4+2][aRow]      = a0.z;
        sA[aCol4*4+3][aRow]      = a0.w;
        sA[aCol4*4+0][aRow + 32] = a1.x;
        sA[aCol4*4+1][aRow + 32] = a1.y;
        sA[aCol4*4+2][aRow + 32] = a1.z;
        sA[aCol4*4+3][aRow + 32] = a1.w;
        *(float4*)&sB[bRow][bCol4*4]      = b0;
        *(float4*)&sB[bRow + 16][bCol4*4] = b1;
        __syncthreads();

        #pragma unroll
        for (int kk = 0; kk < 32; kk++) {
            float ra[4], rb[4];
            #pragma unroll
            for (int i = 0; i < 4; i++) ra[i] = sA[kk][ty*4 + i];
            #pragma unroll
            for (int j = 0; j < 4; j++) rb[j] = sB[kk][tx*4 + j];
            #pragma unroll
            for (int i = 0; i < 4; i++)
                #pragma unroll
                for (int j = 0; j < 4; j++)
                    acc[i][j] += ra[i] * rb[j];
        }
    }

    #pragma unroll
    for (int i = 0; i < 4; i++) {
        int m = m0 + ty*4 + i;
        #pragma unroll
        for (int j = 0; j < 4; j++) {
            int n = n0 + tx*4 + j;
            if (MODE == 0) {
                C[(size_t)m * N + n] = acc[i][j];
            } else {
                int bb = m >> 11;         // row / 2048
                int t  = m & (T_LEN - 1);
                int hh = n >> 6;
                int dd = n & 63;
                C[(((size_t)bb * N_HEADS + hh) * T_LEN + t) * D_K + dd] = acc[i][j];
            }
        }
    }
}

// ============================================================
// Kernel 3: causal flash attention (fp32)
// grid (16 q-tiles, 32 bh), 128 threads, one query row per thread.
// KV processed in tiles of 32 through shared memory.
// Output written directly in [B,T,512] layout.
// ============================================================
__global__ __launch_bounds__(128, 1) void attn_kernel(
    const float* __restrict__ q,
    const float* __restrict__ k,
    const float* __restrict__ v,
    float* __restrict__ o_out)
{
    int qt  = blockIdx.x;          // 0..15
    int bh  = blockIdx.y;          // 0..31
    int b   = bh >> 3;
    int h   = bh & 7;
    int row = threadIdx.x;         // 0..127
    int qi  = qt * 128 + row;

    // load scaled q row into registers
    float qreg[64];
    {
        const float4* q4 = (const float4*)(q + ((size_t)bh * T_LEN + qi) * D_K);
        #pragma unroll
        for (int i = 0; i < 16; i++) {
            float4 t = q4[i];
            qreg[i*4+0] = t.x * 0.125f;
            qreg[i*4+1] = t.y * 0.125f;
            qreg[i*4+2] = t.z * 0.125f;
            qreg[i*4+3] = t.w * 0.125f;
        }
    }

    float m = -1e30f, l = 0.0f;
    float o[64];
    #pragma unroll
    for (int d = 0; d < 64; d++) o[d] = 0.0f;

    __shared__ float sK[32][64];
    __shared__ float sV[32][64];

    int ntiles = (qt + 1) * 4;     // cover kv up to (qt+1)*128
    for (int tile = 0; tile < ntiles; tile++) {
        int k0 = tile * 32;
        __syncthreads();
        {
            const float4* K4 = (const float4*)(k + ((size_t)bh * T_LEN + k0) * D_K);
            const float4* V4 = (const float4*)(v + ((size_t)bh * T_LEN + k0) * D_K);
            float4* sK4 = (float4*)&sK[0][0];
            float4* sV4 = (float4*)&sV[0][0];
            #pragma unroll
            for (int i = 0; i < 4; i++) {
                sK4[threadIdx.x + i * 128] = K4[threadIdx.x + i * 128];
                sV4[threadIdx.x + i * 128] = V4[threadIdx.x + i * 128];
            }
        }
        __syncthreads();

        float s[32];
        #pragma unroll
        for (int j = 0; j < 32; j++) {
            float acc = 0.0f;
            #pragma unroll
            for (int d = 0; d < 64; d++) acc += qreg[d] * sK[j][d];
            s[j] = (k0 + j <= qi) ? acc : -1e30f;
        }

        float tm = m;
        #pragma unroll
        for (int j = 0; j < 32; j++) tm = fmaxf(tm, s[j]);

        float factor = __expf(m - tm);
        l *= factor;
        #pragma unroll
        for (int d = 0; d < 64; d++) o[d] *= factor;

        #pragma unroll
        for (int j = 0; j < 32; j++) {
            float p = __expf(s[j] - tm);
            l += p;
            #pragma unroll
            for (int d = 0; d < 64; d++) o[d] += p * sV[j][d];
        }
        m = tm;
    }

    float inv = 1.0f / l;
    float* op = o_out + ((size_t)b * T_LEN + qi) * D_MODEL + h * D_K;
    #pragma unroll
    for (int i = 0; i < 16; i++) {
        float4 t;
        t.x = o[i*4+0] * inv;
        t.y = o[i*4+1] * inv;
        t.z = o[i*4+2] * inv;
        t.w = o[i*4+3] * inv;
        ((float4*)op)[i] = t;
    }
}

// ============================================================
// Kernel 4: residual + LayerNorm(eps=1e-6) + outer residual
// out = LN(y + h) * g2 + b2 + x
// ============================================================
__global__ __launch_bounds__(128) void ln2_kernel(
    const float* __restrict__ y,
    const float* __restrict__ h,
    const float* __restrict__ x,
    const float* __restrict__ g2,
    const float* __restrict__ b2,
    float* __restrict__ out)
{
    int r   = blockIdx.x;
    int tid = threadIdx.x;
    float4 yv = ((const float4*)(y + (size_t)r * D_MODEL))[tid];
    float4 hv = ((const float4*)(h + (size_t)r * D_MODEL))[tid];
    float4 tv;
    tv.x = yv.x + hv.x; tv.y = yv.y + hv.y;
    tv.z = yv.z + hv.z; tv.w = yv.w + hv.w;

    float sum = tv.x + tv.y + tv.z + tv.w;
    float sq  = tv.x*tv.x + tv.y*tv.y + tv.z*tv.z + tv.w*tv.w;
    #pragma unroll
    for (int off = 16; off; off >>= 1) {
        sum += __shfl_xor_sync(0xffffffffu, sum, off);
        sq  += __shfl_xor_sync(0xffffffffu, sq,  off);
    }
    __shared__ float s1[4], s2[4];
    if ((tid & 31) == 0) { s1[tid >> 5] = sum; s2[tid >> 5] = sq; }
    __syncthreads();
    sum = s1[0] + s1[1] + s1[2] + s1[3];
    sq  = s2[0] + s2[1] + s2[2] + s2[3];

    float mean = sum * (1.0f / D_MODEL);
    float var  = sq  * (1.0f / D_MODEL) - mean * mean;
    float rstd = rsqrtf(var + 1e-6f);

    float4 xv = ((const float4*)(x + (size_t)r * D_MODEL))[tid];
    const float* tp = (const float*)&tv;
    const float* xp = (const float*)&xv;
    int c0 = tid * 4;
    float4 ov;
    float* op = (float*)&ov;
    #pragma unroll
    for (int u = 0; u < 4; u++) {
        int c = c0 + u;
        op[u] = (tp[u] - mean) * rstd * g2[c] + b2[c] + xp[u];
    }
    ((float4*)(out + (size_t)r * D_MODEL))[tid] = ov;
}

// ============================================================
// launch
// ============================================================
extern "C" void kernel_launch(void* const* d_in, const int* in_sizes, int n_in,
                              void* d_out, int out_size)
{
    const float* x   = (const float*)d_in[0];
    const float* g1  = (const float*)d_in[1];
    const float* b1  = (const float*)d_in[2];
    const float* wq  = (const float*)d_in[3];
    const float* wk  = (const float*)d_in[4];
    const float* wv  = (const float*)d_in[5];
    const float* wfc = (const float*)d_in[6];
    const float* g2  = (const float*)d_in[7];
    const float* b2  = (const float*)d_in[8];
    float* out = (float*)d_out;

    float *ph, *pq, *pk, *pv, *po, *py;
    cudaGetSymbolAddress((void**)&ph, g_h);
    cudaGetSymbolAddress((void**)&pq, g_q);
    cudaGetSymbolAddress((void**)&pk, g_k);
    cudaGetSymbolAddress((void**)&pv, g_v);
    cudaGetSymbolAddress((void**)&po, g_o);
    cudaGetSymbolAddress((void**)&py, g_y);

    ln1_pe_kernel<<<NROWS, 128>>>(x, g1, b1, ph);

    dim3 gg(D_MODEL / 64, NROWS / 64);   // (8, 128)
    gemm_k<1><<<gg, 256>>>(ph, wq, pq);
    gemm_k<1><<<gg, 256>>>(ph, wk, pk);
    gemm_k<1><<<gg, 256>>>(ph, wv, pv);

    attn_kernel<<<dim3(T_LEN / 128, BATCH * N_HEADS), 128>>>(pq, pk, pv, po);

    gemm_k<0><<<gg, 256>>>(po, wfc, py);

    ln2_kernel<<<NROWS, 128>>>(py, ph, x, g2, b2, out);
}